// round 1
// baseline (speedup 1.0000x reference)
#include <cuda_runtime.h>
#include <cuda_bf16.h>

// ---------------------------------------------------------------------------
// Problem constants
// ---------------------------------------------------------------------------
#define BB      2
#define LL      4096
#define DMODEL  768
#define DSTATE  16
#define DCONV   4
#define DINNER  1536
#define DTRANK  48
#define NTOT    (BB*LL)          // 8192 flattened (b,l)
#define EPROJ   (DTRANK + 2*DSTATE)  // 80

// ---------------------------------------------------------------------------
// Scratch (static device globals; no runtime allocation allowed)
// ---------------------------------------------------------------------------
__device__ float g_xz  [2*DINNER*NTOT];   // in_proj output, [e][n] e<3072
__device__ float g_xca [DINNER*NTOT];     // conv+silu branch a
__device__ float g_xcb [DINNER*NTOT];     // conv+silu branch b (orig coords, anti-causal)
__device__ float g_dbla[EPROJ*NTOT];
__device__ float g_dblb[EPROJ*NTOT];
__device__ float g_da  [DINNER*NTOT];     // delta a (softplus applied)
__device__ float g_db  [DINNER*NTOT];
__device__ float g_ya  [DINNER*NTOT];
__device__ float g_yb  [DINNER*NTOT];
__device__ float g_y   [DINNER*NTOT];     // combined gated y

// ---------------------------------------------------------------------------
// Math helpers
// ---------------------------------------------------------------------------
__device__ __forceinline__ float softplus_f(float x) {
    return (x > 20.f) ? x : log1pf(__expf(x));
}
__device__ __forceinline__ float silu_f(float x) {
    return x / (1.f + __expf(-x));
}

// ---------------------------------------------------------------------------
// Generic tiled FP32 GEMM: C[M,N] = A(M,K) * B(K,N)
//   TA: A(m,k) stored at A[k*lda + m]  (else A[m*lda + k])
//   TB: B(k,n) stored at B[n*ldb + k]  (else B[k*ldb + n])
//   EPI==1: C = softplus(acc + bias[m])
// ---------------------------------------------------------------------------
template<int BM, int BN, int BK, int TM, int TN, bool TA, bool TB, int EPI>
__global__ __launch_bounds__((BM/TM)*(BN/TN))
void gemm_kernel(const float* __restrict__ A, const float* __restrict__ B,
                 float* __restrict__ C, int M, int N, int K,
                 int lda, int ldb, int ldc,
                 const float* __restrict__ bias)
{
    constexpr int THREADS = (BM/TM)*(BN/TN);
    __shared__ float As[BK][BM];
    __shared__ float Bs[BK][BN];

    const int tid = threadIdx.x;
    const int tx  = tid % (BN/TN);
    const int ty  = tid / (BN/TN);
    const int m0  = blockIdx.y * BM;
    const int n0  = blockIdx.x * BN;

    float acc[TM][TN];
#pragma unroll
    for (int i = 0; i < TM; ++i)
#pragma unroll
        for (int j = 0; j < TN; ++j) acc[i][j] = 0.f;

    for (int k0 = 0; k0 < K; k0 += BK) {
        // ---- load A tile -> As[k][m]
        if (!TA) {
#pragma unroll
            for (int i = 0; i < (BM*BK)/THREADS; ++i) {
                int idx = tid + i*THREADS;
                int k = idx % BK, m = idx / BK;
                int gm = m0 + m;
                As[k][m] = (gm < M) ? A[(long)gm*lda + (k0+k)] : 0.f;
            }
        } else {
#pragma unroll
            for (int i = 0; i < (BM*BK)/THREADS; ++i) {
                int idx = tid + i*THREADS;
                int m = idx % BM, k = idx / BM;
                int gm = m0 + m;
                As[k][m] = (gm < M) ? A[(long)(k0+k)*lda + gm] : 0.f;
            }
        }
        // ---- load B tile -> Bs[k][n]
        if (!TB) {
#pragma unroll
            for (int i = 0; i < (BN*BK)/THREADS; ++i) {
                int idx = tid + i*THREADS;
                int n = idx % BN, k = idx / BN;
                int gn = n0 + n;
                Bs[k][n] = (gn < N) ? B[(long)(k0+k)*ldb + gn] : 0.f;
            }
        } else {
#pragma unroll
            for (int i = 0; i < (BN*BK)/THREADS; ++i) {
                int idx = tid + i*THREADS;
                int k = idx % BK, n = idx / BK;
                int gn = n0 + n;
                Bs[k][n] = (gn < N) ? B[(long)gn*ldb + (k0+k)] : 0.f;
            }
        }
        __syncthreads();

#pragma unroll
        for (int k = 0; k < BK; ++k) {
            float a[TM], b[TN];
#pragma unroll
            for (int i = 0; i < TM; ++i) a[i] = As[k][ty*TM + i];
#pragma unroll
            for (int j = 0; j < TN; ++j) b[j] = Bs[k][tx*TN + j];
#pragma unroll
            for (int i = 0; i < TM; ++i)
#pragma unroll
                for (int j = 0; j < TN; ++j)
                    acc[i][j] = fmaf(a[i], b[j], acc[i][j]);
        }
        __syncthreads();
    }

#pragma unroll
    for (int i = 0; i < TM; ++i) {
        int gm = m0 + ty*TM + i;
        if (gm >= M) continue;
#pragma unroll
        for (int j = 0; j < TN; ++j) {
            int gn = n0 + tx*TN + j;
            if (gn >= N) continue;
            float v = acc[i][j];
            if (EPI == 1) v = softplus_f(v + bias[gm]);
            C[(long)gm*ldc + gn] = v;
        }
    }
}

// ---------------------------------------------------------------------------
// Depthwise conv(w=4) + SiLU.  dir=0: causal, dir=1: anti-causal (branch b in
// original coordinates).  x rows are [d][b*L + l].
// ---------------------------------------------------------------------------
__global__ void conv_silu_kernel(const float* __restrict__ x,
                                 const float* __restrict__ w,
                                 const float* __restrict__ bias,
                                 float* __restrict__ out, int dir)
{
    long idx = (long)blockIdx.x * blockDim.x + threadIdx.x;
    if (idx >= (long)DINNER*NTOT) return;
    int d = (int)(idx / NTOT);
    int n = (int)(idx % NTOT);
    int b = n / LL;
    int l = n % LL;
    const float* xr = x + (long)d*NTOT + (long)b*LL;
    float acc = bias[d];
    if (dir == 0) {
#pragma unroll
        for (int k = 0; k < DCONV; ++k) {
            int li = l - (DCONV-1) + k;
            if (li >= 0) acc = fmaf(w[d*DCONV + k], xr[li], acc);
        }
    } else {
#pragma unroll
        for (int k = 0; k < DCONV; ++k) {
            int li = l + (DCONV-1) - k;
            if (li < LL) acc = fmaf(w[d*DCONV + k], xr[li], acc);
        }
    }
    out[idx] = silu_f(acc);
}

// ---------------------------------------------------------------------------
// Selective scan: one 16-lane half-warp per (b,d). lane = state index.
// dir=+1 forward (branch a), dir=-1 backward (branch b, orig coords).
// ---------------------------------------------------------------------------
__global__ __launch_bounds__(256)
void scan_kernel(const float* __restrict__ u, const float* __restrict__ delta,
                 const float* __restrict__ Bm, const float* __restrict__ Cm,
                 const float* __restrict__ A_log, const float* __restrict__ Dv,
                 float* __restrict__ y, int dir)
{
    int tid    = threadIdx.x;
    int lane16 = tid & 15;
    int unit   = blockIdx.x * (blockDim.x >> 4) + (tid >> 4);   // 0..3071
    int b = unit / DINNER;
    int d = unit % DINNER;

    long base = (long)d*NTOT + (long)b*LL;
    const float* uR = u     + base;
    const float* dR = delta + base;
    const float* BR = Bm + (long)lane16*NTOT + (long)b*LL;
    const float* CR = Cm + (long)lane16*NTOT + (long)b*LL;
    float* yR = y + base;

    float A  = -__expf(A_log[d*DSTATE + lane16]);
    float Dd = Dv[d];
    float h  = 0.f;

    for (int q = 0; q < LL/4; ++q) {
        int l0 = (dir > 0) ? q*4 : (LL - 4 - q*4);
        float4 u4 = *(const float4*)(uR + l0);
        float4 d4 = *(const float4*)(dR + l0);
        float4 B4 = *(const float4*)(BR + l0);
        float4 C4 = *(const float4*)(CR + l0);
        float uu[4] = {u4.x, u4.y, u4.z, u4.w};
        float dd[4] = {d4.x, d4.y, d4.z, d4.w};
        float bb[4] = {B4.x, B4.y, B4.z, B4.w};
        float cc[4] = {C4.x, C4.y, C4.z, C4.w};
#pragma unroll
        for (int j = 0; j < 4; ++j) {
            int jj = (dir > 0) ? j : 3 - j;
            float ut = uu[jj];
            float dt = dd[jj];
            float dA = __expf(dt * A);
            h = fmaf(dA, h, dt * ut * bb[jj]);
            float p = h * cc[jj];
            p += __shfl_xor_sync(0xffffffffu, p, 1);
            p += __shfl_xor_sync(0xffffffffu, p, 2);
            p += __shfl_xor_sync(0xffffffffu, p, 4);
            p += __shfl_xor_sync(0xffffffffu, p, 8);
            if (lane16 == 0) yR[l0 + jj] = fmaf(ut, Dd, p);
        }
    }
}

// ---------------------------------------------------------------------------
// Combine: y = (ya + yb) * silu(z),  z = xz rows [1536..3071]
// ---------------------------------------------------------------------------
__global__ void combine_kernel(const float* __restrict__ ya,
                               const float* __restrict__ yb,
                               const float* __restrict__ xz,
                               float* __restrict__ y)
{
    long idx = (long)blockIdx.x * blockDim.x + threadIdx.x;
    if (idx >= (long)DINNER*NTOT) return;
    float z = xz[(long)DINNER*NTOT + idx];
    y[idx] = (ya[idx] + yb[idx]) * silu_f(z);
}

// ---------------------------------------------------------------------------
// Host launcher
// ---------------------------------------------------------------------------
static float* sym_addr(const void* sym) {
    void* p = nullptr;
    cudaGetSymbolAddress(&p, sym);
    return (float*)p;
}

extern "C" void kernel_launch(void* const* d_in, const int* in_sizes, int n_in,
                              void* d_out, int out_size)
{
    const float* hidden    = (const float*)d_in[0];   // (B,L,768)
    const float* in_proj   = (const float*)d_in[1];   // (3072,768)
    const float* out_proj  = (const float*)d_in[2];   // (768,1536)
    const float* conv_w_a  = (const float*)d_in[3];   // (1536,4)
    const float* conv_b_a  = (const float*)d_in[4];
    const float* conv_w_b  = (const float*)d_in[5];
    const float* conv_b_b  = (const float*)d_in[6];
    const float* xproj_a   = (const float*)d_in[7];   // (80,1536)
    const float* xproj_b   = (const float*)d_in[8];
    const float* dtproj_a  = (const float*)d_in[9];   // (1536,48)
    const float* dtproj_b  = (const float*)d_in[10];
    const float* dtbias_a  = (const float*)d_in[11];
    const float* dtbias_b  = (const float*)d_in[12];
    const float* A_a_log   = (const float*)d_in[13];  // (1536,16)
    const float* A_b_log   = (const float*)d_in[14];
    const float* D_a       = (const float*)d_in[15];
    const float* D_b       = (const float*)d_in[16];
    float* out             = (float*)d_out;           // (B,L,768)

    float* xz   = sym_addr(g_xz);
    float* xca  = sym_addr(g_xca);
    float* xcb  = sym_addr(g_xcb);
    float* dbla = sym_addr(g_dbla);
    float* dblb = sym_addr(g_dblb);
    float* da   = sym_addr(g_da);
    float* db   = sym_addr(g_db);
    float* ya   = sym_addr(g_ya);
    float* yb   = sym_addr(g_yb);
    float* yc   = sym_addr(g_y);

    // 1) xz[e][n] = in_proj(3072x768) @ hidden^T(768x8192)
    {
        dim3 grid(NTOT/128, (2*DINNER)/128);
        gemm_kernel<128,128,8,8,8,false,true,0><<<grid, 256>>>(
            in_proj, hidden, xz, 2*DINNER, NTOT, DMODEL,
            DMODEL, DMODEL, NTOT, nullptr);
    }

    // 2) depthwise conv + SiLU (branch a causal, branch b anti-causal)
    {
        long total = (long)DINNER*NTOT;
        int blocks = (int)((total + 255) / 256);
        conv_silu_kernel<<<blocks, 256>>>(xz, conv_w_a, conv_b_a, xca, 0);
        conv_silu_kernel<<<blocks, 256>>>(xz, conv_w_b, conv_b_b, xcb, 1);
    }

    // 3) dbl[80][n] = x_proj(80x1536) @ xconv(1536x8192)
    {
        dim3 grid(NTOT/128, (EPROJ + 31)/32);
        gemm_kernel<32,128,8,2,8,false,false,0><<<grid, 256>>>(
            xproj_a, xca, dbla, EPROJ, NTOT, DINNER, DINNER, NTOT, NTOT, nullptr);
        gemm_kernel<32,128,8,2,8,false,false,0><<<grid, 256>>>(
            xproj_b, xcb, dblb, EPROJ, NTOT, DINNER, DINNER, NTOT, NTOT, nullptr);
    }

    // 4) delta = softplus(dt_proj(1536x48) @ dbl[0:48] + bias)
    {
        dim3 grid(NTOT/128, DINNER/128);
        gemm_kernel<128,128,8,8,8,false,false,1><<<grid, 256>>>(
            dtproj_a, dbla, da, DINNER, NTOT, DTRANK, DTRANK, NTOT, NTOT, dtbias_a);
        gemm_kernel<128,128,8,8,8,false,false,1><<<grid, 256>>>(
            dtproj_b, dblb, db, DINNER, NTOT, DTRANK, DTRANK, NTOT, NTOT, dtbias_b);
    }

    // 5) selective scans (a forward, b backward)
    {
        int units  = BB * DINNER;          // 3072 half-warps
        int blocks = units / 16;           // 256 threads -> 16 units/block
        scan_kernel<<<blocks, 256>>>(xca, da,
            dbla + (long)DTRANK*NTOT, dbla + (long)(DTRANK+DSTATE)*NTOT,
            A_a_log, D_a, ya, +1);
        scan_kernel<<<blocks, 256>>>(xcb, db,
            dblb + (long)DTRANK*NTOT, dblb + (long)(DTRANK+DSTATE)*NTOT,
            A_b_log, D_b, yb, -1);
    }

    // 6) combine + gate
    {
        long total = (long)DINNER*NTOT;
        int blocks = (int)((total + 255) / 256);
        combine_kernel<<<blocks, 256>>>(ya, yb, xz, yc);
    }

    // 7) out[n][o] = y^T(8192x1536) @ out_proj^T(1536x768)
    {
        dim3 grid(DMODEL/128, NTOT/128);
        gemm_kernel<128,128,8,8,8,true,true,0><<<grid, 256>>>(
            yc, out_proj, out, NTOT, DMODEL, DINNER,
            NTOT, DINNER, DMODEL, nullptr);
    }
}

// round 2
// speedup vs baseline: 1.2997x; 1.2997x over previous
#include <cuda_runtime.h>
#include <cuda_bf16.h>
#include <cstdint>

// ---------------------------------------------------------------------------
// Problem constants
// ---------------------------------------------------------------------------
#define BB      2
#define LL      4096
#define DMODEL  768
#define DSTATE  16
#define DCONV   4
#define DINNER  1536
#define DTRANK  48
#define NTOT    (BB*LL)              // 8192 flattened (b,l)
#define EPROJ   (DTRANK + 2*DSTATE)  // 80

// ---------------------------------------------------------------------------
// Scratch (static device globals; no runtime allocation allowed)
// ---------------------------------------------------------------------------
__device__ float g_xz  [2*DINNER*NTOT];   // in_proj output, [e][n] e<3072
__device__ float g_xca [DINNER*NTOT];     // conv+silu branch a
__device__ float g_xcb [DINNER*NTOT];     // conv+silu branch b (anti-causal)
__device__ float g_dbla[EPROJ*NTOT];
__device__ float g_dblb[EPROJ*NTOT];
__device__ float g_da  [DINNER*NTOT];     // delta a (softplus applied)
__device__ float g_db  [DINNER*NTOT];
__device__ float g_ya  [DINNER*NTOT];
__device__ float g_yb  [DINNER*NTOT];
__device__ float g_y   [DINNER*NTOT];     // combined gated y

// ---------------------------------------------------------------------------
// Math helpers
// ---------------------------------------------------------------------------
__device__ __forceinline__ float softplus_f(float x) {
    return (x > 20.f) ? x : log1pf(__expf(x));
}
__device__ __forceinline__ float silu_f(float x) {
    return x / (1.f + __expf(-x));
}
__device__ __forceinline__ void split_tf32(float x, uint32_t& hi, uint32_t& lo) {
    uint32_t h;
    asm("cvt.rna.tf32.f32 %0, %1;" : "=r"(h) : "f"(x));
    float hf = __uint_as_float(h);
    float lf = x - hf;
    asm("cvt.rna.tf32.f32 %0, %1;" : "=r"(lo) : "f"(lf));
    hi = h;
}
__device__ __forceinline__ void mma_tf32(float c[4], const uint32_t a[4], const uint32_t b[2]) {
    asm volatile(
        "mma.sync.aligned.m16n8k8.row.col.f32.tf32.tf32.f32 "
        "{%0,%1,%2,%3}, {%4,%5,%6,%7}, {%8,%9}, {%0,%1,%2,%3};"
        : "+f"(c[0]), "+f"(c[1]), "+f"(c[2]), "+f"(c[3])
        : "r"(a[0]), "r"(a[1]), "r"(a[2]), "r"(a[3]), "r"(b[0]), "r"(b[1]));
}

// ---------------------------------------------------------------------------
// TF32 tensor-core GEMM with 3x split (full fp32 accuracy).
//   C[M,N] = A(M,K) @ B(K,N)
//   A always row-major [m][lda] (contiguous k).
//   TB=false: B[k][ldb] (contiguous n).  TB=true: B[n][ldb] (contiguous k).
//   CT=true:  store C transposed: C[n*ldc + m]  (else C[m*ldc + n]).
//   EPI==1:   C = softplus(acc + bias[m]).
// Block tile 128x128, BK=16, 8 warps, warp tile 64x32.
// Requires: N % 128 == 0, K % 16 == 0 (M guarded).
// ---------------------------------------------------------------------------
template<int EPI, bool TB, bool CT>
__global__ __launch_bounds__(256, 2)
void gemm_tf32(const float* __restrict__ A, const float* __restrict__ B,
               float* __restrict__ C, int M, int N, int K,
               int lda, int ldb, int ldc, const float* __restrict__ bias)
{
    // stride 136 floats -> bank = (8*k + x) % 32, conflict-free for frag loads
    __shared__ uint32_t sAh[16][136];
    __shared__ uint32_t sAl[16][136];
    __shared__ uint32_t sBh[16][136];
    __shared__ uint32_t sBl[16][136];

    const int tid = threadIdx.x;
    const int w   = tid >> 5;
    const int wm  = w >> 2;          // 0..1 -> 64-row slab
    const int wn  = w & 3;           // 0..3 -> 32-col slab
    const int lane = tid & 31;
    const int g   = lane >> 2;       // 0..7
    const int t   = lane & 3;        // 0..3
    const int m0  = blockIdx.y * 128;
    const int n0  = blockIdx.x * 128;

    float acc[4][4][4];
#pragma unroll
    for (int i = 0; i < 4; ++i)
#pragma unroll
        for (int j = 0; j < 4; ++j)
#pragma unroll
            for (int c = 0; c < 4; ++c) acc[i][j][c] = 0.f;

    for (int k0 = 0; k0 < K; k0 += 16) {
        // ---- A tile: 128m x 16k.  512 float4 slots, 2 per thread.
#pragma unroll
        for (int p = 0; p < 2; ++p) {
            int idx = tid + p*256;
            int m  = idx >> 2;
            int k4 = idx & 3;
            int gm = m0 + m;
            float4 v = make_float4(0.f,0.f,0.f,0.f);
            if (gm < M) v = *(const float4*)(A + (long)gm*lda + (k0 + k4*4));
            float vv[4] = {v.x, v.y, v.z, v.w};
#pragma unroll
            for (int j = 0; j < 4; ++j) {
                uint32_t hi, lo;
                split_tf32(vv[j], hi, lo);
                sAh[k4*4 + j][m] = hi;
                sAl[k4*4 + j][m] = lo;
            }
        }
        // ---- B tile: 16k x 128n.
        if (!TB) {
#pragma unroll
            for (int p = 0; p < 2; ++p) {
                int idx = tid + p*256;
                int k  = idx >> 5;
                int nf = idx & 31;
                float4 v = *(const float4*)(B + (long)(k0 + k)*ldb + (n0 + nf*4));
                float vv[4] = {v.x, v.y, v.z, v.w};
#pragma unroll
                for (int j = 0; j < 4; ++j) {
                    uint32_t hi, lo;
                    split_tf32(vv[j], hi, lo);
                    sBh[k][nf*4 + j] = hi;
                    sBl[k][nf*4 + j] = lo;
                }
            }
        } else {
#pragma unroll
            for (int p = 0; p < 2; ++p) {
                int idx = tid + p*256;
                int n  = idx & 127;
                int k4 = idx >> 7;   // 0..3
                float4 v = *(const float4*)(B + (long)(n0 + n)*ldb + (k0 + k4*4));
                float vv[4] = {v.x, v.y, v.z, v.w};
#pragma unroll
                for (int j = 0; j < 4; ++j) {
                    uint32_t hi, lo;
                    split_tf32(vv[j], hi, lo);
                    sBh[k4*4 + j][n] = hi;
                    sBl[k4*4 + j][n] = lo;
                }
            }
        }
        __syncthreads();

#pragma unroll
        for (int k8 = 0; k8 < 2; ++k8) {
            const int kt = k8*8 + t;
            uint32_t bh[4][2], bl[4][2];
#pragma unroll
            for (int nt = 0; nt < 4; ++nt) {
                int nn = wn*32 + nt*8 + g;
                bh[nt][0] = sBh[kt][nn];   bh[nt][1] = sBh[kt+4][nn];
                bl[nt][0] = sBl[kt][nn];   bl[nt][1] = sBl[kt+4][nn];
            }
#pragma unroll
            for (int mt = 0; mt < 4; ++mt) {
                int mm = wm*64 + mt*16 + g;
                uint32_t ah[4] = { sAh[kt][mm], sAh[kt][mm+8],
                                   sAh[kt+4][mm], sAh[kt+4][mm+8] };
                uint32_t al[4] = { sAl[kt][mm], sAl[kt][mm+8],
                                   sAl[kt+4][mm], sAl[kt+4][mm+8] };
#pragma unroll
                for (int nt = 0; nt < 4; ++nt) {
                    mma_tf32(acc[mt][nt], ah, bh[nt]);   // hi*hi
                    mma_tf32(acc[mt][nt], ah, bl[nt]);   // hi*lo
                    mma_tf32(acc[mt][nt], al, bh[nt]);   // lo*hi
                }
            }
        }
        __syncthreads();
    }

    // ---- epilogue
#pragma unroll
    for (int mt = 0; mt < 4; ++mt) {
#pragma unroll
        for (int nt = 0; nt < 4; ++nt) {
            int gm = m0 + wm*64 + mt*16 + g;
            int gn = n0 + wn*32 + nt*8 + 2*t;
            float c0 = acc[mt][nt][0], c1 = acc[mt][nt][1];
            float c2 = acc[mt][nt][2], c3 = acc[mt][nt][3];
            if (EPI == 1) {
                if (gm < M) {
                    float b0 = bias[gm];
                    c0 = softplus_f(c0 + b0);
                    c1 = softplus_f(c1 + b0);
                }
                if (gm + 8 < M) {
                    float b1 = bias[gm + 8];
                    c2 = softplus_f(c2 + b1);
                    c3 = softplus_f(c3 + b1);
                }
            }
            if (!CT) {
                if (gm < M) {
                    C[(long)gm*ldc + gn]     = c0;
                    C[(long)gm*ldc + gn + 1] = c1;
                }
                if (gm + 8 < M) {
                    C[(long)(gm+8)*ldc + gn]     = c2;
                    C[(long)(gm+8)*ldc + gn + 1] = c3;
                }
            } else {
                if (gm < M) {
                    C[(long)gn*ldc + gm]       = c0;
                    C[(long)(gn+1)*ldc + gm]   = c1;
                }
                if (gm + 8 < M) {
                    C[(long)gn*ldc + gm + 8]     = c2;
                    C[(long)(gn+1)*ldc + gm + 8] = c3;
                }
            }
        }
    }
}

// ---------------------------------------------------------------------------
// Depthwise conv(w=4) + SiLU.  dir=0: causal, dir=1: anti-causal.
// ---------------------------------------------------------------------------
__global__ void conv_silu_kernel(const float* __restrict__ x,
                                 const float* __restrict__ w,
                                 const float* __restrict__ bias,
                                 float* __restrict__ out, int dir)
{
    long idx = (long)blockIdx.x * blockDim.x + threadIdx.x;
    if (idx >= (long)DINNER*NTOT) return;
    int d = (int)(idx / NTOT);
    int n = (int)(idx % NTOT);
    int b = n / LL;
    int l = n % LL;
    const float* xr = x + (long)d*NTOT + (long)b*LL;
    float acc = bias[d];
    if (dir == 0) {
#pragma unroll
        for (int k = 0; k < DCONV; ++k) {
            int li = l - (DCONV-1) + k;
            if (li >= 0) acc = fmaf(w[d*DCONV + k], xr[li], acc);
        }
    } else {
#pragma unroll
        for (int k = 0; k < DCONV; ++k) {
            int li = l + (DCONV-1) - k;
            if (li < LL) acc = fmaf(w[d*DCONV + k], xr[li], acc);
        }
    }
    out[idx] = silu_f(acc);
}

// ---------------------------------------------------------------------------
// Selective scan: one 16-lane half-warp per (b,d). lane = state index.
// ---------------------------------------------------------------------------
__global__ __launch_bounds__(256)
void scan_kernel(const float* __restrict__ u, const float* __restrict__ delta,
                 const float* __restrict__ Bm, const float* __restrict__ Cm,
                 const float* __restrict__ A_log, const float* __restrict__ Dv,
                 float* __restrict__ y, int dir)
{
    int tid    = threadIdx.x;
    int lane16 = tid & 15;
    int unit   = blockIdx.x * (blockDim.x >> 4) + (tid >> 4);
    int b = unit / DINNER;
    int d = unit % DINNER;

    long base = (long)d*NTOT + (long)b*LL;
    const float* uR = u     + base;
    const float* dR = delta + base;
    const float* BR = Bm + (long)lane16*NTOT + (long)b*LL;
    const float* CR = Cm + (long)lane16*NTOT + (long)b*LL;
    float* yR = y + base;

    float A  = -__expf(A_log[d*DSTATE + lane16]);
    float Dd = Dv[d];
    float h  = 0.f;

    for (int q = 0; q < LL/4; ++q) {
        int l0 = (dir > 0) ? q*4 : (LL - 4 - q*4);
        float4 u4 = *(const float4*)(uR + l0);
        float4 d4 = *(const float4*)(dR + l0);
        float4 B4 = *(const float4*)(BR + l0);
        float4 C4 = *(const float4*)(CR + l0);
        float uu[4] = {u4.x, u4.y, u4.z, u4.w};
        float dd[4] = {d4.x, d4.y, d4.z, d4.w};
        float bb[4] = {B4.x, B4.y, B4.z, B4.w};
        float cc[4] = {C4.x, C4.y, C4.z, C4.w};
#pragma unroll
        for (int j = 0; j < 4; ++j) {
            int jj = (dir > 0) ? j : 3 - j;
            float ut = uu[jj];
            float dt = dd[jj];
            float dA = __expf(dt * A);
            h = fmaf(dA, h, dt * ut * bb[jj]);
            float p = h * cc[jj];
            p += __shfl_xor_sync(0xffffffffu, p, 1);
            p += __shfl_xor_sync(0xffffffffu, p, 2);
            p += __shfl_xor_sync(0xffffffffu, p, 4);
            p += __shfl_xor_sync(0xffffffffu, p, 8);
            if (lane16 == 0) yR[l0 + jj] = fmaf(ut, Dd, p);
        }
    }
}

// ---------------------------------------------------------------------------
// Combine: y = (ya + yb) * silu(z)
// ---------------------------------------------------------------------------
__global__ void combine_kernel(const float* __restrict__ ya,
                               const float* __restrict__ yb,
                               const float* __restrict__ xz,
                               float* __restrict__ y)
{
    long idx = (long)blockIdx.x * blockDim.x + threadIdx.x;
    if (idx >= (long)DINNER*NTOT) return;
    float z = xz[(long)DINNER*NTOT + idx];
    y[idx] = (ya[idx] + yb[idx]) * silu_f(z);
}

// ---------------------------------------------------------------------------
// Host launcher
// ---------------------------------------------------------------------------
static float* sym_addr(const void* sym) {
    void* p = nullptr;
    cudaGetSymbolAddress(&p, sym);
    return (float*)p;
}

extern "C" void kernel_launch(void* const* d_in, const int* in_sizes, int n_in,
                              void* d_out, int out_size)
{
    const float* hidden    = (const float*)d_in[0];   // (B,L,768)
    const float* in_proj   = (const float*)d_in[1];   // (3072,768)
    const float* out_proj  = (const float*)d_in[2];   // (768,1536)
    const float* conv_w_a  = (const float*)d_in[3];   // (1536,4)
    const float* conv_b_a  = (const float*)d_in[4];
    const float* conv_w_b  = (const float*)d_in[5];
    const float* conv_b_b  = (const float*)d_in[6];
    const float* xproj_a   = (const float*)d_in[7];   // (80,1536)
    const float* xproj_b   = (const float*)d_in[8];
    const float* dtproj_a  = (const float*)d_in[9];   // (1536,48)
    const float* dtproj_b  = (const float*)d_in[10];
    const float* dtbias_a  = (const float*)d_in[11];
    const float* dtbias_b  = (const float*)d_in[12];
    const float* A_a_log   = (const float*)d_in[13];  // (1536,16)
    const float* A_b_log   = (const float*)d_in[14];
    const float* D_a       = (const float*)d_in[15];
    const float* D_b       = (const float*)d_in[16];
    float* out             = (float*)d_out;           // (B,L,768)

    float* xz   = sym_addr(g_xz);
    float* xca  = sym_addr(g_xca);
    float* xcb  = sym_addr(g_xcb);
    float* dbla = sym_addr(g_dbla);
    float* dblb = sym_addr(g_dblb);
    float* da   = sym_addr(g_da);
    float* db   = sym_addr(g_db);
    float* ya   = sym_addr(g_ya);
    float* yb   = sym_addr(g_yb);
    float* yc   = sym_addr(g_y);

    // 1) xz[e][n] = in_proj(3072x768) @ hidden^T(768x8192)   (B transposed)
    {
        dim3 grid(NTOT/128, (2*DINNER)/128);
        gemm_tf32<0,true,false><<<grid, 256>>>(
            in_proj, hidden, xz, 2*DINNER, NTOT, DMODEL,
            DMODEL, DMODEL, NTOT, nullptr);
    }

    // 2) depthwise conv + SiLU
    {
        long total = (long)DINNER*NTOT;
        int blocks = (int)((total + 255) / 256);
        conv_silu_kernel<<<blocks, 256>>>(xz, conv_w_a, conv_b_a, xca, 0);
        conv_silu_kernel<<<blocks, 256>>>(xz, conv_w_b, conv_b_b, xcb, 1);
    }

    // 3) dbl[80][n] = x_proj(80x1536) @ xconv(1536x8192)
    {
        dim3 grid(NTOT/128, 1);
        gemm_tf32<0,false,false><<<grid, 256>>>(
            xproj_a, xca, dbla, EPROJ, NTOT, DINNER, DINNER, NTOT, NTOT, nullptr);
        gemm_tf32<0,false,false><<<grid, 256>>>(
            xproj_b, xcb, dblb, EPROJ, NTOT, DINNER, DINNER, NTOT, NTOT, nullptr);
    }

    // 4) delta = softplus(dt_proj(1536x48) @ dbl[0:48] + bias)
    {
        dim3 grid(NTOT/128, DINNER/128);
        gemm_tf32<1,false,false><<<grid, 256>>>(
            dtproj_a, dbla, da, DINNER, NTOT, DTRANK, DTRANK, NTOT, NTOT, dtbias_a);
        gemm_tf32<1,false,false><<<grid, 256>>>(
            dtproj_b, dblb, db, DINNER, NTOT, DTRANK, DTRANK, NTOT, NTOT, dtbias_b);
    }

    // 5) selective scans (a forward, b backward)
    {
        int units  = BB * DINNER;
        int blocks = units / 16;
        scan_kernel<<<blocks, 256>>>(xca, da,
            dbla + (long)DTRANK*NTOT, dbla + (long)(DTRANK+DSTATE)*NTOT,
            A_a_log, D_a, ya, +1);
        scan_kernel<<<blocks, 256>>>(xcb, db,
            dblb + (long)DTRANK*NTOT, dblb + (long)(DTRANK+DSTATE)*NTOT,
            A_b_log, D_b, yb, -1);
    }

    // 6) combine + gate
    {
        long total = (long)DINNER*NTOT;
        int blocks = (int)((total + 255) / 256);
        combine_kernel<<<blocks, 256>>>(ya, yb, xz, yc);
    }

    // 7) outT[o][n] = out_proj(768x1536) @ y(1536x8192), stored transposed
    {
        dim3 grid(NTOT/128, DMODEL/128);
        gemm_tf32<0,false,true><<<grid, 256>>>(
            out_proj, yc, out, DMODEL, NTOT, DINNER,
            DINNER, NTOT, DMODEL, nullptr);
    }
}

// round 3
// speedup vs baseline: 2.3593x; 1.8152x over previous
#include <cuda_runtime.h>
#include <cuda_bf16.h>
#include <cstdint>

// ---------------------------------------------------------------------------
// Problem constants
// ---------------------------------------------------------------------------
#define BB      2
#define LL      4096
#define DMODEL  768
#define DSTATE  16
#define DCONV   4
#define DINNER  1536
#define DTRANK  48
#define NTOT    (BB*LL)              // 8192
#define EPROJ   (DTRANK + 2*DSTATE)  // 80

// ---------------------------------------------------------------------------
// Scratch (static device globals)
// ---------------------------------------------------------------------------
__device__ uint32_t g_hid_p [NTOT*DMODEL];        // hidden, packed split
__device__ uint32_t g_inp_p [2*DINNER*DMODEL];    // in_proj weights packed
__device__ uint32_t g_outp_p[DMODEL*DINNER];      // out_proj packed
__device__ uint32_t g_xpa_p [EPROJ*DINNER];
__device__ uint32_t g_xpb_p [EPROJ*DINNER];
__device__ uint32_t g_dtpa_p[DINNER*DTRANK];
__device__ uint32_t g_dtpb_p[DINNER*DTRANK];

__device__ float    g_xz   [2*DINNER*NTOT];       // in_proj out fp32 (x | z)
__device__ uint32_t g_xca_p[DINNER*NTOT];         // conv+silu a, packed
__device__ uint32_t g_xcb_p[DINNER*NTOT];         // conv+silu b, packed
__device__ uint32_t g_dtina[DTRANK*NTOT];         // dbl rows 0..47, packed
__device__ uint32_t g_dtinb[DTRANK*NTOT];
__device__ float    g_bca  [2*DSTATE*NTOT];       // B (16 rows) + C (16 rows) fp32
__device__ float    g_bcb  [2*DSTATE*NTOT];
__device__ uint32_t g_da_p [DINNER*NTOT];         // delta a packed
__device__ uint32_t g_db_p [DINNER*NTOT];
__device__ float    g_ya   [DINNER*NTOT];
__device__ float    g_yb   [DINNER*NTOT];
__device__ uint32_t g_yp   [DINNER*NTOT];         // gated y packed

// ---------------------------------------------------------------------------
// Helpers
// ---------------------------------------------------------------------------
__device__ __forceinline__ float softplus_f(float x) {
    return (x > 20.f) ? x : log1pf(__expf(x));
}
__device__ __forceinline__ float silu_f(float x) {
    return x / (1.f + __expf(-x));
}
__device__ __forceinline__ uint32_t pack_bf2(float x) {
    __nv_bfloat16 h = __float2bfloat16(x);
    float hf = __bfloat162float(h);
    __nv_bfloat16 l = __float2bfloat16(x - hf);
    return ((uint32_t)__bfloat16_as_ushort(l) << 16) |
           (uint32_t)__bfloat16_as_ushort(h);
}
__device__ __forceinline__ float unpack_bf2(uint32_t w) {
    return __bfloat162float(__ushort_as_bfloat16((unsigned short)(w & 0xffffu))) +
           __bfloat162float(__ushort_as_bfloat16((unsigned short)(w >> 16)));
}
__device__ __forceinline__ void mma_bf16(float c[4], const uint32_t a[4], const uint32_t b[2]) {
    asm volatile(
        "mma.sync.aligned.m16n8k16.row.col.f32.bf16.bf16.f32 "
        "{%0,%1,%2,%3}, {%4,%5,%6,%7}, {%8,%9}, {%0,%1,%2,%3};"
        : "+f"(c[0]), "+f"(c[1]), "+f"(c[2]), "+f"(c[3])
        : "r"(a[0]), "r"(a[1]), "r"(a[2]), "r"(a[3]), "r"(b[0]), "r"(b[1]));
}

// ---------------------------------------------------------------------------
// bf16 3-pass GEMM on pre-packed inputs.
//   Element format: uint32 = (bf16(lo)<<16) | bf16(hi),  value = hi + lo.
//   C[M,N] = A(M,K) @ B(K,N)
//   A packed [m][lda] (k contiguous).
//   TB=false: B packed [k][ldb].  TB=true: B packed [n][ldb] (k contiguous).
//   EPI 0: fp32 C[m][n] (CT: C[n][m]).
//   EPI 1: softplus(acc + bias[m]) -> packed C2.
//   EPI 2: rows<48 -> packed C2 ; rows 48..79 -> fp32 C (row-48).
// Block 128x128, BK=16, 256 thr, 8 warps (2x4), warp tile 64x32.
// ---------------------------------------------------------------------------
struct GArgs {
    const uint32_t* A;
    const uint32_t* B;
    float*          C;
    uint32_t*       C2;
    const float*    bias;
};

template<int EPI, bool TB, bool CT>
__global__ __launch_bounds__(256, 2)
void gemm_bf16(GArgs g0, GArgs g1, int M, int N, int K,
               int lda, int ldb, int ldc)
{
    __shared__ uint32_t sAh[2][8][140];
    __shared__ uint32_t sAl[2][8][140];
    __shared__ uint32_t sBh[2][8][140];
    __shared__ uint32_t sBl[2][8][140];

    const GArgs ga = blockIdx.z ? g1 : g0;
    const uint32_t* __restrict__ A = ga.A;
    const uint32_t* __restrict__ B = ga.B;

    const int tid  = threadIdx.x;
    const int w    = tid >> 5;
    const int wm   = w >> 2;
    const int wn   = w & 3;
    const int lane = tid & 31;
    const int g    = lane >> 2;
    const int t    = lane & 3;
    const int m0   = blockIdx.y * 128;
    const int n0   = blockIdx.x * 128;

    float acc[4][4][4];
#pragma unroll
    for (int i = 0; i < 4; ++i)
#pragma unroll
        for (int j = 0; j < 4; ++j)
#pragma unroll
            for (int c = 0; c < 4; ++c) acc[i][j][c] = 0.f;

    uint4 ra[2];   // A staging: 2 slots (m, 4k each)
    uint4 rb[2];   // B staging

    // ---- load helpers (to regs) ----
    auto loadA = [&](int k0) {
#pragma unroll
        for (int p = 0; p < 2; ++p) {
            int idx = tid + p*256;
            int m  = idx >> 2;
            int kq = idx & 3;
            int gm = m0 + m;
            ra[p] = (gm < M) ? *(const uint4*)(A + (long)gm*lda + k0 + 4*kq)
                             : make_uint4(0,0,0,0);
        }
    };
    auto loadB = [&](int k0) {
        if (!TB) {
            int kp = tid >> 5;        // 0..7
            int nf = tid & 31;
            rb[0] = *(const uint4*)(B + (long)(k0 + 2*kp)*ldb + n0 + 4*nf);
            rb[1] = *(const uint4*)(B + (long)(k0 + 2*kp + 1)*ldb + n0 + 4*nf);
        } else {
#pragma unroll
            for (int p = 0; p < 2; ++p) {
                int idx = tid + p*256;
                int n  = idx >> 2;
                int kq = idx & 3;
                rb[p] = *(const uint4*)(B + (long)(n0 + n)*ldb + k0 + 4*kq);
            }
        }
    };
    auto stsA = [&](int st) {
#pragma unroll
        for (int p = 0; p < 2; ++p) {
            int idx = tid + p*256;
            int m  = idx >> 2;
            int kq = idx & 3;
            uint4 v = ra[p];
            sAh[st][2*kq  ][m] = __byte_perm(v.x, v.y, 0x5410);
            sAl[st][2*kq  ][m] = __byte_perm(v.x, v.y, 0x7632);
            sAh[st][2*kq+1][m] = __byte_perm(v.z, v.w, 0x5410);
            sAl[st][2*kq+1][m] = __byte_perm(v.z, v.w, 0x7632);
        }
    };
    auto stsB = [&](int st) {
        if (!TB) {
            int kp = tid >> 5;
            int nf = tid & 31;
            uint4 r0 = rb[0], r1 = rb[1];
            uint4 h, l;
            h.x = __byte_perm(r0.x, r1.x, 0x5410); l.x = __byte_perm(r0.x, r1.x, 0x7632);
            h.y = __byte_perm(r0.y, r1.y, 0x5410); l.y = __byte_perm(r0.y, r1.y, 0x7632);
            h.z = __byte_perm(r0.z, r1.z, 0x5410); l.z = __byte_perm(r0.z, r1.z, 0x7632);
            h.w = __byte_perm(r0.w, r1.w, 0x5410); l.w = __byte_perm(r0.w, r1.w, 0x7632);
            *(uint4*)&sBh[st][kp][4*nf] = h;
            *(uint4*)&sBl[st][kp][4*nf] = l;
        } else {
#pragma unroll
            for (int p = 0; p < 2; ++p) {
                int idx = tid + p*256;
                int n  = idx >> 2;
                int kq = idx & 3;
                uint4 v = rb[p];
                sBh[st][2*kq  ][n] = __byte_perm(v.x, v.y, 0x5410);
                sBl[st][2*kq  ][n] = __byte_perm(v.x, v.y, 0x7632);
                sBh[st][2*kq+1][n] = __byte_perm(v.z, v.w, 0x5410);
                sBl[st][2*kq+1][n] = __byte_perm(v.z, v.w, 0x7632);
            }
        }
    };

    // ---- pipeline ----
    loadA(0); loadB(0);
    stsA(0);  stsB(0);
    __syncthreads();

    const int iters = K / 16;
    for (int it = 0; it < iters; ++it) {
        const int cur  = it & 1;
        const bool more = (it + 1 < iters);
        if (more) { loadA((it+1)*16); loadB((it+1)*16); }

        // compute on stage cur
        uint32_t bh[4][2], bl[4][2];
#pragma unroll
        for (int nt = 0; nt < 4; ++nt) {
            int nn = wn*32 + nt*8 + g;
            bh[nt][0] = sBh[cur][t  ][nn];
            bh[nt][1] = sBh[cur][t+4][nn];
            bl[nt][0] = sBl[cur][t  ][nn];
            bl[nt][1] = sBl[cur][t+4][nn];
        }
#pragma unroll
        for (int mt = 0; mt < 4; ++mt) {
            int mm = wm*64 + mt*16 + g;
            uint32_t ah[4] = { sAh[cur][t][mm],   sAh[cur][t][mm+8],
                               sAh[cur][t+4][mm], sAh[cur][t+4][mm+8] };
            uint32_t al[4] = { sAl[cur][t][mm],   sAl[cur][t][mm+8],
                               sAl[cur][t+4][mm], sAl[cur][t+4][mm+8] };
#pragma unroll
            for (int nt = 0; nt < 4; ++nt) {
                mma_bf16(acc[mt][nt], ah, bh[nt]);
                mma_bf16(acc[mt][nt], ah, bl[nt]);
                mma_bf16(acc[mt][nt], al, bh[nt]);
            }
        }

        if (more) {
            stsA(cur ^ 1); stsB(cur ^ 1);
            __syncthreads();
        }
    }

    // ---- epilogue ----
#pragma unroll
    for (int mt = 0; mt < 4; ++mt) {
#pragma unroll
        for (int nt = 0; nt < 4; ++nt) {
            int gm = m0 + wm*64 + mt*16 + g;
            int gn = n0 + wn*32 + nt*8 + 2*t;
            float c0 = acc[mt][nt][0], c1 = acc[mt][nt][1];
            float c2 = acc[mt][nt][2], c3 = acc[mt][nt][3];
            if (EPI == 0) {
                if (!CT) {
                    if (gm < M) {
                        ga.C[(long)gm*ldc + gn]     = c0;
                        ga.C[(long)gm*ldc + gn + 1] = c1;
                    }
                    if (gm + 8 < M) {
                        ga.C[(long)(gm+8)*ldc + gn]     = c2;
                        ga.C[(long)(gm+8)*ldc + gn + 1] = c3;
                    }
                } else {
                    if (gm < M) {
                        ga.C[(long)gn*ldc + gm]       = c0;
                        ga.C[(long)(gn+1)*ldc + gm]   = c1;
                    }
                    if (gm + 8 < M) {
                        ga.C[(long)gn*ldc + gm + 8]     = c2;
                        ga.C[(long)(gn+1)*ldc + gm + 8] = c3;
                    }
                }
            } else if (EPI == 1) {
                if (gm < M) {
                    float b0 = ga.bias[gm];
                    ga.C2[(long)gm*ldc + gn]     = pack_bf2(softplus_f(c0 + b0));
                    ga.C2[(long)gm*ldc + gn + 1] = pack_bf2(softplus_f(c1 + b0));
                }
                if (gm + 8 < M) {
                    float b1 = ga.bias[gm + 8];
                    ga.C2[(long)(gm+8)*ldc + gn]     = pack_bf2(softplus_f(c2 + b1));
                    ga.C2[(long)(gm+8)*ldc + gn + 1] = pack_bf2(softplus_f(c3 + b1));
                }
            } else { // EPI 2: dt rows packed, B/C rows fp32
                if (gm < DTRANK) {
                    ga.C2[(long)gm*ldc + gn]     = pack_bf2(c0);
                    ga.C2[(long)gm*ldc + gn + 1] = pack_bf2(c1);
                } else if (gm < EPROJ) {
                    ga.C[(long)(gm - DTRANK)*ldc + gn]     = c0;
                    ga.C[(long)(gm - DTRANK)*ldc + gn + 1] = c1;
                }
                if (gm + 8 < DTRANK) {
                    ga.C2[(long)(gm+8)*ldc + gn]     = pack_bf2(c2);
                    ga.C2[(long)(gm+8)*ldc + gn + 1] = pack_bf2(c3);
                } else if (gm + 8 < EPROJ) {
                    ga.C[(long)(gm+8 - DTRANK)*ldc + gn]     = c2;
                    ga.C[(long)(gm+8 - DTRANK)*ldc + gn + 1] = c3;
                }
            }
        }
    }
}

// ---------------------------------------------------------------------------
// Pre-split: fp32 -> packed bf16x2, 7 segments fused in one launch
// ---------------------------------------------------------------------------
__global__ void split_multi(const float* s0, uint32_t* d0, long c0,
                            const float* s1, uint32_t* d1, long c1,
                            const float* s2, uint32_t* d2, long c2,
                            const float* s3, uint32_t* d3, long c3,
                            const float* s4, uint32_t* d4, long c4,
                            const float* s5, uint32_t* d5, long c5,
                            const float* s6, uint32_t* d6, long c6)
{
    long q = ((long)blockIdx.x * blockDim.x + threadIdx.x) * 4;
    const float* s; uint32_t* d;
    if      (q < c0) { s = s0; d = d0; }
    else if ((q -= c0) < c1) { s = s1; d = d1; }
    else if ((q -= c1) < c2) { s = s2; d = d2; }
    else if ((q -= c2) < c3) { s = s3; d = d3; }
    else if ((q -= c3) < c4) { s = s4; d = d4; }
    else if ((q -= c4) < c5) { s = s5; d = d5; }
    else if ((q -= c5) < c6) { s = s6; d = d6; }
    else return;
    float4 v = *(const float4*)(s + q);
    uint4 o;
    o.x = pack_bf2(v.x); o.y = pack_bf2(v.y);
    o.z = pack_bf2(v.z); o.w = pack_bf2(v.w);
    *(uint4*)(d + q) = o;
}

// ---------------------------------------------------------------------------
// Fused depthwise conv(w=4)+SiLU, both branches, packed output.
// ---------------------------------------------------------------------------
__global__ __launch_bounds__(256)
void conv_silu_both(const float* __restrict__ x,
                    const float* __restrict__ wa, const float* __restrict__ ba,
                    const float* __restrict__ wb, const float* __restrict__ bb,
                    uint32_t* __restrict__ oa, uint32_t* __restrict__ ob)
{
    long q = (long)blockIdx.x * blockDim.x + threadIdx.x;   // 4 l per thread
    const long PERD = NTOT/4;
    int d  = (int)(q / PERD);
    int n4 = (int)(q % PERD);
    int n  = n4 * 4;
    int b  = n / LL;
    int l0 = n % LL;

    const float* xr = x + (long)d*NTOT + (long)b*LL;
    float4 prev = (l0 >= 4)      ? *(const float4*)(xr + l0 - 4) : make_float4(0,0,0,0);
    float4 cur  =                  *(const float4*)(xr + l0);
    float4 next = (l0 + 4 < LL)  ? *(const float4*)(xr + l0 + 4) : make_float4(0,0,0,0);

    float xa[8] = {prev.x, prev.y, prev.z, prev.w, cur.x, cur.y, cur.z, cur.w};
    float xb[8] = {cur.x, cur.y, cur.z, cur.w, next.x, next.y, next.z, next.w};

    float wav[4], wbv[4];
#pragma unroll
    for (int k = 0; k < 4; ++k) { wav[k] = wa[d*4+k]; wbv[k] = wb[d*4+k]; }
    float bav = ba[d], bbv = bb[d];

    uint4 outa, outb;
    uint32_t* pa = &outa.x;
    uint32_t* pb = &outb.x;
#pragma unroll
    for (int j = 0; j < 4; ++j) {
        float sa = bav, sb = bbv;
#pragma unroll
        for (int k = 0; k < 4; ++k) {
            sa = fmaf(wav[k], xa[j + 1 + k], sa);
            sb = fmaf(wbv[k], xb[j + 3 - k], sb);
        }
        pa[j] = pack_bf2(silu_f(sa));
        pb[j] = pack_bf2(silu_f(sb));
    }
    *(uint4*)(oa + (long)d*NTOT + n) = outa;
    *(uint4*)(ob + (long)d*NTOT + n) = outb;
}

// ---------------------------------------------------------------------------
// Selective scan, both branches batched. 16-lane half-warp per (branch,b,d).
// u, delta packed; B,C fp32; y fp32.
// ---------------------------------------------------------------------------
__global__ __launch_bounds__(256)
void scan_both(const uint32_t* __restrict__ ua, const uint32_t* __restrict__ da,
               const float* __restrict__ bca, const float* __restrict__ Ala,
               const float* __restrict__ Dva, float* __restrict__ ya,
               const uint32_t* __restrict__ ub, const uint32_t* __restrict__ db,
               const float* __restrict__ bcb, const float* __restrict__ Alb,
               const float* __restrict__ Dvb, float* __restrict__ yb)
{
    int tid    = threadIdx.x;
    int lane16 = tid & 15;
    int unit   = blockIdx.x * (blockDim.x >> 4) + (tid >> 4);  // 0..6143
    int branch = unit >= BB*DINNER;
    int u2     = unit - branch*BB*DINNER;
    int b = u2 / DINNER;
    int d = u2 % DINNER;

    const uint32_t* uP = branch ? ub : ua;
    const uint32_t* dP = branch ? db : da;
    const float*    bc = branch ? bcb : bca;
    const float*    Al = branch ? Alb : Ala;
    const float*    Dv = branch ? Dvb : Dva;
    float*          yP = branch ? yb : ya;
    int dir = branch ? -1 : 1;

    long base = (long)d*NTOT + (long)b*LL;
    const uint32_t* uR = uP + base;
    const uint32_t* dR = dP + base;
    const float* BR = bc + (long)lane16*NTOT + (long)b*LL;
    const float* CR = bc + (long)(DSTATE + lane16)*NTOT + (long)b*LL;
    float* yR = yP + base;

    float A  = -__expf(Al[d*DSTATE + lane16]);
    float Dd = Dv[d];
    float h  = 0.f;

    for (int q = 0; q < LL/4; ++q) {
        int l0 = (dir > 0) ? q*4 : (LL - 4 - q*4);
        uint4  u4 = *(const uint4*)(uR + l0);
        uint4  d4 = *(const uint4*)(dR + l0);
        float4 B4 = *(const float4*)(BR + l0);
        float4 C4 = *(const float4*)(CR + l0);
        float uu[4] = {unpack_bf2(u4.x), unpack_bf2(u4.y), unpack_bf2(u4.z), unpack_bf2(u4.w)};
        float dd[4] = {unpack_bf2(d4.x), unpack_bf2(d4.y), unpack_bf2(d4.z), unpack_bf2(d4.w)};
        float bb[4] = {B4.x, B4.y, B4.z, B4.w};
        float cc[4] = {C4.x, C4.y, C4.z, C4.w};
        float yout[4];
#pragma unroll
        for (int j = 0; j < 4; ++j) {
            int jj = (dir > 0) ? j : 3 - j;
            float ut = uu[jj];
            float dt = dd[jj];
            float dA = __expf(dt * A);
            h = fmaf(dA, h, dt * ut * bb[jj]);
            float p = h * cc[jj];
            p += __shfl_xor_sync(0xffffffffu, p, 1);
            p += __shfl_xor_sync(0xffffffffu, p, 2);
            p += __shfl_xor_sync(0xffffffffu, p, 4);
            p += __shfl_xor_sync(0xffffffffu, p, 8);
            yout[jj] = fmaf(ut, Dd, p);
        }
        if (lane16 == 0)
            *(float4*)(yR + l0) = make_float4(yout[0], yout[1], yout[2], yout[3]);
    }
}

// ---------------------------------------------------------------------------
// Combine: y = (ya + yb) * silu(z) -> packed
// ---------------------------------------------------------------------------
__global__ void combine_kernel(const float* __restrict__ ya,
                               const float* __restrict__ yb,
                               const float* __restrict__ xz,
                               uint32_t* __restrict__ y)
{
    long q = ((long)blockIdx.x * blockDim.x + threadIdx.x) * 4;
    if (q >= (long)DINNER*NTOT) return;
    float4 a = *(const float4*)(ya + q);
    float4 b = *(const float4*)(yb + q);
    float4 z = *(const float4*)(xz + (long)DINNER*NTOT + q);
    uint4 o;
    o.x = pack_bf2((a.x + b.x) * silu_f(z.x));
    o.y = pack_bf2((a.y + b.y) * silu_f(z.y));
    o.z = pack_bf2((a.z + b.z) * silu_f(z.z));
    o.w = pack_bf2((a.w + b.w) * silu_f(z.w));
    *(uint4*)(y + q) = o;
}

// ---------------------------------------------------------------------------
// Host launcher
// ---------------------------------------------------------------------------
template<typename T>
static T* sym_addr(const void* sym) {
    void* p = nullptr;
    cudaGetSymbolAddress(&p, sym);
    return (T*)p;
}

extern "C" void kernel_launch(void* const* d_in, const int* in_sizes, int n_in,
                              void* d_out, int out_size)
{
    const float* hidden    = (const float*)d_in[0];
    const float* in_proj   = (const float*)d_in[1];
    const float* out_proj  = (const float*)d_in[2];
    const float* conv_w_a  = (const float*)d_in[3];
    const float* conv_b_a  = (const float*)d_in[4];
    const float* conv_w_b  = (const float*)d_in[5];
    const float* conv_b_b  = (const float*)d_in[6];
    const float* xproj_a   = (const float*)d_in[7];
    const float* xproj_b   = (const float*)d_in[8];
    const float* dtproj_a  = (const float*)d_in[9];
    const float* dtproj_b  = (const float*)d_in[10];
    const float* dtbias_a  = (const float*)d_in[11];
    const float* dtbias_b  = (const float*)d_in[12];
    const float* A_a_log   = (const float*)d_in[13];
    const float* A_b_log   = (const float*)d_in[14];
    const float* D_a       = (const float*)d_in[15];
    const float* D_b       = (const float*)d_in[16];
    float* out             = (float*)d_out;

    uint32_t* hid_p  = sym_addr<uint32_t>(g_hid_p);
    uint32_t* inp_p  = sym_addr<uint32_t>(g_inp_p);
    uint32_t* outp_p = sym_addr<uint32_t>(g_outp_p);
    uint32_t* xpa_p  = sym_addr<uint32_t>(g_xpa_p);
    uint32_t* xpb_p  = sym_addr<uint32_t>(g_xpb_p);
    uint32_t* dtpa_p = sym_addr<uint32_t>(g_dtpa_p);
    uint32_t* dtpb_p = sym_addr<uint32_t>(g_dtpb_p);
    float*    xz     = sym_addr<float>(g_xz);
    uint32_t* xca_p  = sym_addr<uint32_t>(g_xca_p);
    uint32_t* xcb_p  = sym_addr<uint32_t>(g_xcb_p);
    uint32_t* dtina  = sym_addr<uint32_t>(g_dtina);
    uint32_t* dtinb  = sym_addr<uint32_t>(g_dtinb);
    float*    bca    = sym_addr<float>(g_bca);
    float*    bcb    = sym_addr<float>(g_bcb);
    uint32_t* da_p   = sym_addr<uint32_t>(g_da_p);
    uint32_t* db_p   = sym_addr<uint32_t>(g_db_p);
    float*    ya     = sym_addr<float>(g_ya);
    float*    yb     = sym_addr<float>(g_yb);
    uint32_t* yp     = sym_addr<uint32_t>(g_yp);

    // 0) split weights + hidden into packed bf16x2
    {
        long c0 = (long)NTOT*DMODEL;        // hidden
        long c1 = (long)2*DINNER*DMODEL;    // in_proj
        long c2 = (long)DMODEL*DINNER;      // out_proj
        long c3 = (long)EPROJ*DINNER;       // xproj a
        long c4 = (long)EPROJ*DINNER;       // xproj b
        long c5 = (long)DINNER*DTRANK;      // dtproj a
        long c6 = (long)DINNER*DTRANK;      // dtproj b
        long total = c0+c1+c2+c3+c4+c5+c6;
        int blocks = (int)((total/4 + 255) / 256);
        split_multi<<<blocks, 256>>>(hidden, hid_p, c0, in_proj, inp_p, c1,
                                     out_proj, outp_p, c2, xproj_a, xpa_p, c3,
                                     xproj_b, xpb_p, c4, dtproj_a, dtpa_p, c5,
                                     dtproj_b, dtpb_p, c6);
    }

    // 1) xz = in_proj(3072x768) @ hidden^T(768x8192), fp32 out
    {
        GArgs ga{inp_p, hid_p, xz, nullptr, nullptr};
        dim3 grid(NTOT/128, (2*DINNER)/128, 1);
        gemm_bf16<0,true,false><<<grid, 256>>>(ga, ga, 2*DINNER, NTOT, DMODEL,
                                               DMODEL, DMODEL, NTOT);
    }

    // 2) conv + SiLU, both branches -> packed
    {
        long total = (long)DINNER*NTOT/4;
        conv_silu_both<<<(int)(total/256), 256>>>(xz, conv_w_a, conv_b_a,
                                                  conv_w_b, conv_b_b, xca_p, xcb_p);
    }

    // 3) x_proj both branches: dbl = xproj(80x1536) @ xc(1536x8192)
    //    rows<48 -> packed dtin ; rows 48..79 -> fp32 bc
    {
        GArgs a{xpa_p, xca_p, bca, dtina, nullptr};
        GArgs b{xpb_p, xcb_p, bcb, dtinb, nullptr};
        dim3 grid(NTOT/128, 1, 2);
        gemm_bf16<2,false,false><<<grid, 256>>>(a, b, EPROJ, NTOT, DINNER,
                                                DINNER, NTOT, NTOT);
    }

    // 4) delta = softplus(dtproj(1536x48) @ dtin(48x8192) + bias) -> packed
    {
        GArgs a{dtpa_p, dtina, nullptr, da_p, dtbias_a};
        GArgs b{dtpb_p, dtinb, nullptr, db_p, dtbias_b};
        dim3 grid(NTOT/128, DINNER/128, 2);
        gemm_bf16<1,false,false><<<grid, 256>>>(a, b, DINNER, NTOT, DTRANK,
                                                DTRANK, NTOT, NTOT);
    }

    // 5) both scans in one launch
    {
        int units  = 2 * BB * DINNER;       // 6144
        int blocks = units / 16;
        scan_both<<<blocks, 256>>>(xca_p, da_p, bca, A_a_log, D_a, ya,
                                   xcb_p, db_p, bcb, A_b_log, D_b, yb);
    }

    // 6) combine + gate -> packed
    {
        long total = (long)DINNER*NTOT/4;
        combine_kernel<<<(int)((total + 255)/256), 256>>>(ya, yb, xz, yp);
    }

    // 7) out^T: out_proj(768x1536) @ y(1536x8192), stored C[n][o]
    {
        GArgs ga{outp_p, yp, out, nullptr, nullptr};
        dim3 grid(NTOT/128, DMODEL/128, 1);
        gemm_bf16<0,false,true><<<grid, 256>>>(ga, ga, DMODEL, NTOT, DINNER,
                                               DINNER, NTOT, DMODEL);
    }
}

// round 4
// speedup vs baseline: 2.8741x; 1.2182x over previous
#include <cuda_runtime.h>
#include <cuda_bf16.h>
#include <cstdint>

// ---------------------------------------------------------------------------
// Problem constants
// ---------------------------------------------------------------------------
#define BB      2
#define LL      4096
#define DMODEL  768
#define DSTATE  16
#define DCONV   4
#define DINNER  1536
#define DTRANK  48
#define NTOT    (BB*LL)              // 8192
#define EPROJ   (DTRANK + 2*DSTATE)  // 80

// ---------------------------------------------------------------------------
// Scratch (static device globals)
// ---------------------------------------------------------------------------
__device__ uint32_t g_hid_p [NTOT*DMODEL];        // hidden, packed split
__device__ uint32_t g_inp_p [2*DINNER*DMODEL];    // in_proj weights packed
__device__ uint32_t g_outp_p[DMODEL*DINNER];      // out_proj packed
__device__ uint32_t g_xpa_p [EPROJ*DINNER];
__device__ uint32_t g_xpb_p [EPROJ*DINNER];
__device__ uint32_t g_dtpa_p[DINNER*DTRANK];
__device__ uint32_t g_dtpb_p[DINNER*DTRANK];

__device__ float    g_xz   [2*DINNER*NTOT];       // in_proj out fp32 (x | z)
__device__ uint32_t g_xca_p[DINNER*NTOT];         // conv+silu a, packed
__device__ uint32_t g_xcb_p[DINNER*NTOT];         // conv+silu b, packed
__device__ uint32_t g_dtina[DTRANK*NTOT];         // dbl rows 0..47, packed
__device__ uint32_t g_dtinb[DTRANK*NTOT];
__device__ float    g_bca  [2*DSTATE*NTOT];       // interleaved {B,C} per (n,state)
__device__ float    g_bcb  [2*DSTATE*NTOT];
__device__ uint32_t g_da_p [DINNER*NTOT];         // delta a packed
__device__ uint32_t g_db_p [DINNER*NTOT];
__device__ float    g_ya   [DINNER*NTOT];
__device__ float    g_yb   [DINNER*NTOT];
__device__ uint32_t g_yp   [DINNER*NTOT];         // gated y packed

// ---------------------------------------------------------------------------
// Helpers
// ---------------------------------------------------------------------------
__device__ __forceinline__ float softplus_f(float x) {
    return (x > 20.f) ? x : log1pf(__expf(x));
}
__device__ __forceinline__ float silu_f(float x) {
    return x / (1.f + __expf(-x));
}
__device__ __forceinline__ uint32_t pack_bf2(float x) {
    __nv_bfloat16 h = __float2bfloat16(x);
    float hf = __bfloat162float(h);
    __nv_bfloat16 l = __float2bfloat16(x - hf);
    return ((uint32_t)__bfloat16_as_ushort(l) << 16) |
           (uint32_t)__bfloat16_as_ushort(h);
}
__device__ __forceinline__ float unpack_bf2(uint32_t w) {
    return __bfloat162float(__ushort_as_bfloat16((unsigned short)(w & 0xffffu))) +
           __bfloat162float(__ushort_as_bfloat16((unsigned short)(w >> 16)));
}
__device__ __forceinline__ void mma_bf16(float c[4], const uint32_t a[4], const uint32_t b[2]) {
    asm volatile(
        "mma.sync.aligned.m16n8k16.row.col.f32.bf16.bf16.f32 "
        "{%0,%1,%2,%3}, {%4,%5,%6,%7}, {%8,%9}, {%0,%1,%2,%3};"
        : "+f"(c[0]), "+f"(c[1]), "+f"(c[2]), "+f"(c[3])
        : "r"(a[0]), "r"(a[1]), "r"(a[2]), "r"(a[3]), "r"(b[0]), "r"(b[1]));
}

// ---------------------------------------------------------------------------
// bf16 3-pass GEMM on pre-packed inputs (uint32 = lo<<16|hi, value = hi+lo).
//   C[M,N] = A(M,K) @ B(K,N)
//   A packed [m][lda] (k contiguous).
//   TB=false: B packed [k][ldb].  TB=true: B packed [n][ldb] (k contiguous).
//   EPI 0: fp32 C[m][n] (CT: C[n][m]).
//   EPI 1: softplus(acc + bias[m]) -> packed C2.
//   EPI 2: rows<48 -> packed C2 ; rows 48..79 -> interleaved {B,C} fp32 C.
// Block 128x128, BK=16, 256 thr, 8 warps (2x4), warp tile 64x32.
// Smem entries: uint2{hi_pack, lo_pack}, row stride 132 (264 words = 8 mod 32,
// frag reads provably conflict-free).
// ---------------------------------------------------------------------------
struct GArgs {
    const uint32_t* A;
    const uint32_t* B;
    float*          C;
    uint32_t*       C2;
    const float*    bias;
};

template<int EPI, bool TB, bool CT>
__global__ __launch_bounds__(256, 2)
void gemm_bf16(GArgs g0, GArgs g1, int M, int N, int K,
               int lda, int ldb, int ldc)
{
    __shared__ __align__(16) uint2 sA[2][8][132];
    __shared__ __align__(16) uint2 sB[2][8][132];

    const GArgs ga = blockIdx.z ? g1 : g0;
    const uint32_t* __restrict__ A = ga.A;
    const uint32_t* __restrict__ B = ga.B;

    const int tid  = threadIdx.x;
    const int w    = tid >> 5;
    const int wm   = w >> 2;
    const int wn   = w & 3;
    const int lane = tid & 31;
    const int g    = lane >> 2;
    const int t    = lane & 3;
    const int m0   = blockIdx.y * 128;
    const int n0   = blockIdx.x * 128;

    float acc[4][4][4];
#pragma unroll
    for (int i = 0; i < 4; ++i)
#pragma unroll
        for (int j = 0; j < 4; ++j)
#pragma unroll
            for (int c = 0; c < 4; ++c) acc[i][j][c] = 0.f;

    uint4 ra[2];
    uint4 rb[2];

    auto loadA = [&](int k0) {
#pragma unroll
        for (int p = 0; p < 2; ++p) {
            int idx = tid + p*256;
            int m  = idx >> 2;
            int kq = idx & 3;
            int gm = m0 + m;
            ra[p] = (gm < M) ? *(const uint4*)(A + (long)gm*lda + k0 + 4*kq)
                             : make_uint4(0,0,0,0);
        }
    };
    auto loadB = [&](int k0) {
        if (!TB) {
            int kp = tid >> 5;
            int nf = tid & 31;
            rb[0] = *(const uint4*)(B + (long)(k0 + 2*kp)*ldb + n0 + 4*nf);
            rb[1] = *(const uint4*)(B + (long)(k0 + 2*kp + 1)*ldb + n0 + 4*nf);
        } else {
#pragma unroll
            for (int p = 0; p < 2; ++p) {
                int idx = tid + p*256;
                int n  = idx >> 2;
                int kq = idx & 3;
                rb[p] = *(const uint4*)(B + (long)(n0 + n)*ldb + k0 + 4*kq);
            }
        }
    };
    auto stsA = [&](int st) {
#pragma unroll
        for (int p = 0; p < 2; ++p) {
            int idx = tid + p*256;
            int m  = idx >> 2;
            int kq = idx & 3;
            uint4 v = ra[p];
            sA[st][2*kq  ][m] = make_uint2(__byte_perm(v.x, v.y, 0x5410),
                                           __byte_perm(v.x, v.y, 0x7632));
            sA[st][2*kq+1][m] = make_uint2(__byte_perm(v.z, v.w, 0x5410),
                                           __byte_perm(v.z, v.w, 0x7632));
        }
    };
    auto stsB = [&](int st) {
        if (!TB) {
            int kp = tid >> 5;
            int nf = tid & 31;
            uint4 r0 = rb[0], r1 = rb[1];
            uint4 o0, o1;
            o0.x = __byte_perm(r0.x, r1.x, 0x5410); o0.y = __byte_perm(r0.x, r1.x, 0x7632);
            o0.z = __byte_perm(r0.y, r1.y, 0x5410); o0.w = __byte_perm(r0.y, r1.y, 0x7632);
            o1.x = __byte_perm(r0.z, r1.z, 0x5410); o1.y = __byte_perm(r0.z, r1.z, 0x7632);
            o1.z = __byte_perm(r0.w, r1.w, 0x5410); o1.w = __byte_perm(r0.w, r1.w, 0x7632);
            *(uint4*)&sB[st][kp][4*nf]     = o0;
            *(uint4*)&sB[st][kp][4*nf + 2] = o1;
        } else {
#pragma unroll
            for (int p = 0; p < 2; ++p) {
                int idx = tid + p*256;
                int n  = idx >> 2;
                int kq = idx & 3;
                uint4 v = rb[p];
                sB[st][2*kq  ][n] = make_uint2(__byte_perm(v.x, v.y, 0x5410),
                                               __byte_perm(v.x, v.y, 0x7632));
                sB[st][2*kq+1][n] = make_uint2(__byte_perm(v.z, v.w, 0x5410),
                                               __byte_perm(v.z, v.w, 0x7632));
            }
        }
    };

    loadA(0); loadB(0);
    stsA(0);  stsB(0);
    __syncthreads();

    const int iters = K / 16;
    for (int it = 0; it < iters; ++it) {
        const int cur  = it & 1;
        const bool more = (it + 1 < iters);
        if (more) { loadA((it+1)*16); loadB((it+1)*16); }

        uint32_t bh[4][2], bl[4][2];
#pragma unroll
        for (int nt = 0; nt < 4; ++nt) {
            int nn = wn*32 + nt*8 + g;
            uint2 p0 = sB[cur][t  ][nn];
            uint2 p1 = sB[cur][t+4][nn];
            bh[nt][0] = p0.x; bl[nt][0] = p0.y;
            bh[nt][1] = p1.x; bl[nt][1] = p1.y;
        }
#pragma unroll
        for (int mt = 0; mt < 4; ++mt) {
            int mm = wm*64 + mt*16 + g;
            uint2 a0 = sA[cur][t  ][mm];
            uint2 a1 = sA[cur][t  ][mm+8];
            uint2 a2 = sA[cur][t+4][mm];
            uint2 a3 = sA[cur][t+4][mm+8];
            uint32_t ah[4] = { a0.x, a1.x, a2.x, a3.x };
            uint32_t al[4] = { a0.y, a1.y, a2.y, a3.y };
#pragma unroll
            for (int nt = 0; nt < 4; ++nt) {
                mma_bf16(acc[mt][nt], ah, bh[nt]);
                mma_bf16(acc[mt][nt], ah, bl[nt]);
                mma_bf16(acc[mt][nt], al, bh[nt]);
            }
        }

        if (more) {
            stsA(cur ^ 1); stsB(cur ^ 1);
            __syncthreads();
        }
    }

    // ---- epilogue ----
#pragma unroll
    for (int mt = 0; mt < 4; ++mt) {
#pragma unroll
        for (int nt = 0; nt < 4; ++nt) {
            int gm = m0 + wm*64 + mt*16 + g;
            int gn = n0 + wn*32 + nt*8 + 2*t;
            float c0 = acc[mt][nt][0], c1 = acc[mt][nt][1];
            float c2 = acc[mt][nt][2], c3 = acc[mt][nt][3];
            if (EPI == 0) {
                if (!CT) {
                    if (gm < M) {
                        ga.C[(long)gm*ldc + gn]     = c0;
                        ga.C[(long)gm*ldc + gn + 1] = c1;
                    }
                    if (gm + 8 < M) {
                        ga.C[(long)(gm+8)*ldc + gn]     = c2;
                        ga.C[(long)(gm+8)*ldc + gn + 1] = c3;
                    }
                } else {
                    if (gm < M) {
                        ga.C[(long)gn*ldc + gm]       = c0;
                        ga.C[(long)(gn+1)*ldc + gm]   = c1;
                    }
                    if (gm + 8 < M) {
                        ga.C[(long)gn*ldc + gm + 8]     = c2;
                        ga.C[(long)(gn+1)*ldc + gm + 8] = c3;
                    }
                }
            } else if (EPI == 1) {
                if (gm < M) {
                    float b0 = ga.bias[gm];
                    ga.C2[(long)gm*ldc + gn]     = pack_bf2(softplus_f(c0 + b0));
                    ga.C2[(long)gm*ldc + gn + 1] = pack_bf2(softplus_f(c1 + b0));
                }
                if (gm + 8 < M) {
                    float b1 = ga.bias[gm + 8];
                    ga.C2[(long)(gm+8)*ldc + gn]     = pack_bf2(softplus_f(c2 + b1));
                    ga.C2[(long)(gm+8)*ldc + gn + 1] = pack_bf2(softplus_f(c3 + b1));
                }
            } else { // EPI 2: dt rows -> packed; rows 48..79 -> interleaved {B,C}
                if (gm < DTRANK) {
                    ga.C2[(long)gm*ldc + gn]     = pack_bf2(c0);
                    ga.C2[(long)gm*ldc + gn + 1] = pack_bf2(c1);
                } else if (gm < EPROJ) {
                    int r = gm - DTRANK, s = r & 15, wch = r >> 4;
                    ga.C[(((long)gn*16 + s) << 1) + wch]       = c0;
                    ga.C[(((long)(gn+1)*16 + s) << 1) + wch]   = c1;
                }
                if (gm + 8 < DTRANK) {
                    ga.C2[(long)(gm+8)*ldc + gn]     = pack_bf2(c2);
                    ga.C2[(long)(gm+8)*ldc + gn + 1] = pack_bf2(c3);
                } else if (gm + 8 < EPROJ) {
                    int r = gm + 8 - DTRANK, s = r & 15, wch = r >> 4;
                    ga.C[(((long)gn*16 + s) << 1) + wch]       = c2;
                    ga.C[(((long)(gn+1)*16 + s) << 1) + wch]   = c3;
                }
            }
        }
    }
}

// ---------------------------------------------------------------------------
// Pre-split: fp32 -> packed bf16x2, 7 segments fused
// ---------------------------------------------------------------------------
__global__ void split_multi(const float* s0, uint32_t* d0, long c0,
                            const float* s1, uint32_t* d1, long c1,
                            const float* s2, uint32_t* d2, long c2,
                            const float* s3, uint32_t* d3, long c3,
                            const float* s4, uint32_t* d4, long c4,
                            const float* s5, uint32_t* d5, long c5,
                            const float* s6, uint32_t* d6, long c6)
{
    long q = ((long)blockIdx.x * blockDim.x + threadIdx.x) * 4;
    const float* s; uint32_t* d;
    if      (q < c0) { s = s0; d = d0; }
    else if ((q -= c0) < c1) { s = s1; d = d1; }
    else if ((q -= c1) < c2) { s = s2; d = d2; }
    else if ((q -= c2) < c3) { s = s3; d = d3; }
    else if ((q -= c3) < c4) { s = s4; d = d4; }
    else if ((q -= c4) < c5) { s = s5; d = d5; }
    else if ((q -= c5) < c6) { s = s6; d = d6; }
    else return;
    float4 v = *(const float4*)(s + q);
    uint4 o;
    o.x = pack_bf2(v.x); o.y = pack_bf2(v.y);
    o.z = pack_bf2(v.z); o.w = pack_bf2(v.w);
    *(uint4*)(d + q) = o;
}

// ---------------------------------------------------------------------------
// Fused depthwise conv(w=4)+SiLU, both branches, packed output.
// ---------------------------------------------------------------------------
__global__ __launch_bounds__(256)
void conv_silu_both(const float* __restrict__ x,
                    const float* __restrict__ wa, const float* __restrict__ ba,
                    const float* __restrict__ wb, const float* __restrict__ bb,
                    uint32_t* __restrict__ oa, uint32_t* __restrict__ ob)
{
    long q = (long)blockIdx.x * blockDim.x + threadIdx.x;
    const long PERD = NTOT/4;
    int d  = (int)(q / PERD);
    int n4 = (int)(q % PERD);
    int n  = n4 * 4;
    int b  = n / LL;
    int l0 = n % LL;

    const float* xr = x + (long)d*NTOT + (long)b*LL;
    float4 prev = (l0 >= 4)      ? *(const float4*)(xr + l0 - 4) : make_float4(0,0,0,0);
    float4 cur  =                  *(const float4*)(xr + l0);
    float4 next = (l0 + 4 < LL)  ? *(const float4*)(xr + l0 + 4) : make_float4(0,0,0,0);

    float xa[8] = {prev.x, prev.y, prev.z, prev.w, cur.x, cur.y, cur.z, cur.w};
    float xb[8] = {cur.x, cur.y, cur.z, cur.w, next.x, next.y, next.z, next.w};

    float wav[4], wbv[4];
#pragma unroll
    for (int k = 0; k < 4; ++k) { wav[k] = wa[d*4+k]; wbv[k] = wb[d*4+k]; }
    float bav = ba[d], bbv = bb[d];

    uint4 outa, outb;
    uint32_t* pa = &outa.x;
    uint32_t* pb = &outb.x;
#pragma unroll
    for (int j = 0; j < 4; ++j) {
        float sa = bav, sb = bbv;
#pragma unroll
        for (int k = 0; k < 4; ++k) {
            sa = fmaf(wav[k], xa[j + 1 + k], sa);
            sb = fmaf(wbv[k], xb[j + 3 - k], sb);
        }
        pa[j] = pack_bf2(silu_f(sa));
        pb[j] = pack_bf2(silu_f(sb));
    }
    *(uint4*)(oa + (long)d*NTOT + n) = outa;
    *(uint4*)(ob + (long)d*NTOT + n) = outb;
}

// ---------------------------------------------------------------------------
// Selective scan. One warp = two units (d, d+768), same (branch,b): both
// half-warps traverse the same l sequence, sharing B/C cache lines.
// bc layout: float2 {B,C} at [(b*LL + l)*16 + state].
// ---------------------------------------------------------------------------
__global__ __launch_bounds__(256)
void scan_both(const uint32_t* __restrict__ ua, const uint32_t* __restrict__ da,
               const float* __restrict__ bca, const float* __restrict__ Ala,
               const float* __restrict__ Dva, float* __restrict__ ya,
               const uint32_t* __restrict__ ub, const uint32_t* __restrict__ db,
               const float* __restrict__ bcb, const float* __restrict__ Alb,
               const float* __restrict__ Dvb, float* __restrict__ yb)
{
    const int lane   = threadIdx.x & 31;
    const int lane16 = lane & 15;
    const int h      = lane >> 4;
    int warpId = blockIdx.x * (blockDim.x >> 5) + (threadIdx.x >> 5); // 0..3071

    const int branch = warpId / (BB * (DINNER/2));
    int rem = warpId % (BB * (DINNER/2));
    const int b  = rem / (DINNER/2);
    const int dp = rem % (DINNER/2);
    const int d  = dp + h * (DINNER/2);

    const uint32_t* uP = branch ? ub : ua;
    const uint32_t* dP = branch ? db : da;
    const float*    bc = branch ? bcb : bca;
    const float*    Al = branch ? Alb : Ala;
    const float*    Dv = branch ? Dvb : Dva;
    float*          yP = branch ? yb : ya;
    const bool fwd = (branch == 0);

    long base = (long)d*NTOT + (long)b*LL;
    const uint32_t* uR = uP + base;
    const uint32_t* dR = dP + base;
    const float2*   bcR = (const float2*)bc + ((long)b*LL)*16 + lane16;
    float* yR = yP + base;

    float A  = -__expf(Al[d*DSTATE + lane16]);
    float Dd = Dv[d];
    float hS = 0.f;

    for (int q = 0; q < LL/4; ++q) {
        int l0 = fwd ? q*4 : (LL - 4 - q*4);
        uint4 u4 = *(const uint4*)(uR + l0);
        uint4 d4 = *(const uint4*)(dR + l0);
        float2 s0 = bcR[(long)(l0+0)*16];
        float2 s1 = bcR[(long)(l0+1)*16];
        float2 s2 = bcR[(long)(l0+2)*16];
        float2 s3 = bcR[(long)(l0+3)*16];
        float uu[4] = {unpack_bf2(u4.x), unpack_bf2(u4.y), unpack_bf2(u4.z), unpack_bf2(u4.w)};
        float dd[4] = {unpack_bf2(d4.x), unpack_bf2(d4.y), unpack_bf2(d4.z), unpack_bf2(d4.w)};
        float Bv[4] = {s0.x, s1.x, s2.x, s3.x};
        float Cv[4] = {s0.y, s1.y, s2.y, s3.y};
        float yout[4];
#pragma unroll
        for (int j = 0; j < 4; ++j) {
            int jj = fwd ? j : 3 - j;
            float ut = uu[jj];
            float dt = dd[jj];
            float dA = __expf(dt * A);
            hS = fmaf(dA, hS, dt * ut * Bv[jj]);
            float p = hS * Cv[jj];
            p += __shfl_xor_sync(0xffffffffu, p, 1);
            p += __shfl_xor_sync(0xffffffffu, p, 2);
            p += __shfl_xor_sync(0xffffffffu, p, 4);
            p += __shfl_xor_sync(0xffffffffu, p, 8);
            yout[jj] = fmaf(ut, Dd, p);
        }
        if (lane16 == 0)
            *(float4*)(yR + l0) = make_float4(yout[0], yout[1], yout[2], yout[3]);
    }
}

// ---------------------------------------------------------------------------
// Combine: y = (ya + yb) * silu(z) -> packed
// ---------------------------------------------------------------------------
__global__ void combine_kernel(const float* __restrict__ ya,
                               const float* __restrict__ yb,
                               const float* __restrict__ xz,
                               uint32_t* __restrict__ y)
{
    long q = ((long)blockIdx.x * blockDim.x + threadIdx.x) * 4;
    if (q >= (long)DINNER*NTOT) return;
    float4 a = *(const float4*)(ya + q);
    float4 b = *(const float4*)(yb + q);
    float4 z = *(const float4*)(xz + (long)DINNER*NTOT + q);
    uint4 o;
    o.x = pack_bf2((a.x + b.x) * silu_f(z.x));
    o.y = pack_bf2((a.y + b.y) * silu_f(z.y));
    o.z = pack_bf2((a.z + b.z) * silu_f(z.z));
    o.w = pack_bf2((a.w + b.w) * silu_f(z.w));
    *(uint4*)(y + q) = o;
}

// ---------------------------------------------------------------------------
// Host launcher
// ---------------------------------------------------------------------------
template<typename T>
static T* sym_addr(const void* sym) {
    void* p = nullptr;
    cudaGetSymbolAddress(&p, sym);
    return (T*)p;
}

extern "C" void kernel_launch(void* const* d_in, const int* in_sizes, int n_in,
                              void* d_out, int out_size)
{
    const float* hidden    = (const float*)d_in[0];
    const float* in_proj   = (const float*)d_in[1];
    const float* out_proj  = (const float*)d_in[2];
    const float* conv_w_a  = (const float*)d_in[3];
    const float* conv_b_a  = (const float*)d_in[4];
    const float* conv_w_b  = (const float*)d_in[5];
    const float* conv_b_b  = (const float*)d_in[6];
    const float* xproj_a   = (const float*)d_in[7];
    const float* xproj_b   = (const float*)d_in[8];
    const float* dtproj_a  = (const float*)d_in[9];
    const float* dtproj_b  = (const float*)d_in[10];
    const float* dtbias_a  = (const float*)d_in[11];
    const float* dtbias_b  = (const float*)d_in[12];
    const float* A_a_log   = (const float*)d_in[13];
    const float* A_b_log   = (const float*)d_in[14];
    const float* D_a       = (const float*)d_in[15];
    const float* D_b       = (const float*)d_in[16];
    float* out             = (float*)d_out;

    uint32_t* hid_p  = sym_addr<uint32_t>(g_hid_p);
    uint32_t* inp_p  = sym_addr<uint32_t>(g_inp_p);
    uint32_t* outp_p = sym_addr<uint32_t>(g_outp_p);
    uint32_t* xpa_p  = sym_addr<uint32_t>(g_xpa_p);
    uint32_t* xpb_p  = sym_addr<uint32_t>(g_xpb_p);
    uint32_t* dtpa_p = sym_addr<uint32_t>(g_dtpa_p);
    uint32_t* dtpb_p = sym_addr<uint32_t>(g_dtpb_p);
    float*    xz     = sym_addr<float>(g_xz);
    uint32_t* xca_p  = sym_addr<uint32_t>(g_xca_p);
    uint32_t* xcb_p  = sym_addr<uint32_t>(g_xcb_p);
    uint32_t* dtina  = sym_addr<uint32_t>(g_dtina);
    uint32_t* dtinb  = sym_addr<uint32_t>(g_dtinb);
    float*    bca    = sym_addr<float>(g_bca);
    float*    bcb    = sym_addr<float>(g_bcb);
    uint32_t* da_p   = sym_addr<uint32_t>(g_da_p);
    uint32_t* db_p   = sym_addr<uint32_t>(g_db_p);
    float*    ya     = sym_addr<float>(g_ya);
    float*    yb     = sym_addr<float>(g_yb);
    uint32_t* yp     = sym_addr<uint32_t>(g_yp);

    // 0) split weights + hidden into packed bf16x2
    {
        long c0 = (long)NTOT*DMODEL;
        long c1 = (long)2*DINNER*DMODEL;
        long c2 = (long)DMODEL*DINNER;
        long c3 = (long)EPROJ*DINNER;
        long c4 = (long)EPROJ*DINNER;
        long c5 = (long)DINNER*DTRANK;
        long c6 = (long)DINNER*DTRANK;
        long total = c0+c1+c2+c3+c4+c5+c6;
        int blocks = (int)((total/4 + 255) / 256);
        split_multi<<<blocks, 256>>>(hidden, hid_p, c0, in_proj, inp_p, c1,
                                     out_proj, outp_p, c2, xproj_a, xpa_p, c3,
                                     xproj_b, xpb_p, c4, dtproj_a, dtpa_p, c5,
                                     dtproj_b, dtpb_p, c6);
    }

    // 1) xz = in_proj(3072x768) @ hidden^T(768x8192), fp32 out
    {
        GArgs ga{inp_p, hid_p, xz, nullptr, nullptr};
        dim3 grid(NTOT/128, (2*DINNER)/128, 1);
        gemm_bf16<0,true,false><<<grid, 256>>>(ga, ga, 2*DINNER, NTOT, DMODEL,
                                               DMODEL, DMODEL, NTOT);
    }

    // 2) conv + SiLU, both branches -> packed
    {
        long total = (long)DINNER*NTOT/4;
        conv_silu_both<<<(int)(total/256), 256>>>(xz, conv_w_a, conv_b_a,
                                                  conv_w_b, conv_b_b, xca_p, xcb_p);
    }

    // 3) x_proj both branches: dt rows -> packed, B/C -> interleaved fp32
    {
        GArgs a{xpa_p, xca_p, bca, dtina, nullptr};
        GArgs b{xpb_p, xcb_p, bcb, dtinb, nullptr};
        dim3 grid(NTOT/128, 1, 2);
        gemm_bf16<2,false,false><<<grid, 256>>>(a, b, EPROJ, NTOT, DINNER,
                                                DINNER, NTOT, NTOT);
    }

    // 4) delta = softplus(dtproj(1536x48) @ dtin(48x8192) + bias) -> packed
    {
        GArgs a{dtpa_p, dtina, nullptr, da_p, dtbias_a};
        GArgs b{dtpb_p, dtinb, nullptr, db_p, dtbias_b};
        dim3 grid(NTOT/128, DINNER/128, 2);
        gemm_bf16<1,false,false><<<grid, 256>>>(a, b, DINNER, NTOT, DTRANK,
                                                DTRANK, NTOT, NTOT);
    }

    // 5) both scans in one launch (3072 warps)
    {
        int warps  = 2 * BB * (DINNER/2);    // 3072
        int blocks = warps / 8;              // 256 thr = 8 warps
        scan_both<<<blocks, 256>>>(xca_p, da_p, bca, A_a_log, D_a, ya,
                                   xcb_p, db_p, bcb, A_b_log, D_b, yb);
    }

    // 6) combine + gate -> packed
    {
        long total = (long)DINNER*NTOT/4;
        combine_kernel<<<(int)((total + 255)/256), 256>>>(ya, yb, xz, yp);
    }

    // 7) out^T: out_proj(768x1536) @ y(1536x8192), stored C[n][o]
    {
        GArgs ga{outp_p, yp, out, nullptr, nullptr};
        dim3 grid(NTOT/128, DMODEL/128, 1);
        gemm_bf16<0,false,true><<<grid, 256>>>(ga, ga, DMODEL, NTOT, DINNER,
                                               DINNER, NTOT, DMODEL);
    }
}